// round 5
// baseline (speedup 1.0000x reference)
#include <cuda_runtime.h>
#include <cstdint>

// ROI max pooling (shapes fixed):
//   features: (B=4, C=256, H=50, W=50) fp32;  rois: (R=256, 5) int32 (sniffed)
//   out: (R=256, C=256, PH=7, PW=7) fp32
//
// Pipeline:
//  1) transpose features -> g_featT[b][p][c] (channels contiguous, coalesced)
//  2) decode rois once (dtype sniff + >>4) into g_roi
//  3) pool: block=(r, ph, c-half), thread=channel; pw loop in-thread.
//     MLP trick: bin bounds are block-uniform and max is idempotent, so issue
//     4 clamped-offset loads per row (duplicates harmless) -> 4 loads in
//     flight, no divergence. Tail loop only when binw > 4.

#define RP_B  4
#define RP_C  256
#define RP_H  50
#define RP_W  50
#define RP_P  (RP_H * RP_W)   // 2500
#define RP_R  256
#define RP_PH 7
#define RP_PW 7

__device__ float g_featT[RP_B * RP_P * RP_C];   // 10.24 MB scratch
__device__ int   g_roi[RP_R * 8];               // b,x1,y1,w,h per roi

// ---------------- transpose: (B,C,P) -> (B,P,C) ----------------
__global__ __launch_bounds__(256)
void transpose_kernel(const float* __restrict__ feat)
{
    __shared__ float tile[32][33];
    const int b  = blockIdx.z;
    const int ct = blockIdx.y;          // channel tile 0..7
    const int pt = blockIdx.x;          // position tile 0..78
    const int tx = threadIdx.x & 31;
    const int ty = threadIdx.x >> 5;    // 0..7

    const int p_rd = pt * 32 + tx;
    #pragma unroll
    for (int i = 0; i < 4; ++i) {
        const int c = ct * 32 + ty + i * 8;
        if (p_rd < RP_P)
            tile[ty + i * 8][tx] = feat[((size_t)(b * RP_C + c)) * RP_P + p_rd];
    }
    __syncthreads();

    const int c_wr = ct * 32 + tx;
    #pragma unroll
    for (int i = 0; i < 4; ++i) {
        const int p = pt * 32 + ty + i * 8;
        if (p < RP_P)
            g_featT[((size_t)b * RP_P + p) * RP_C + c_wr] = tile[tx][ty + i * 8];
    }
}

// ---------------- decode rois (1 block, 256 threads) ----------------
__global__ __launch_bounds__(256)
void decode_rois_kernel(const int* __restrict__ rois32)
{
    const int r = threadIdx.x;
    // dtype sniff: int64 layout => all odd 32-bit words are zero high-words
    int odd = 0;
    #pragma unroll
    for (int i = 0; i < 16; ++i) odd |= rois32[2 * i + 1];
    const int is64 = (odd == 0);

    int b, x1, y1, x2, y2;
    if (is64) {
        const int* rp = rois32 + r * 10;
        b = rp[0]; x1 = rp[2] >> 4; y1 = rp[4] >> 4; x2 = rp[6] >> 4; y2 = rp[8] >> 4;
    } else {
        const int* rp = rois32 + r * 5;
        b = rp[0]; x1 = rp[1] >> 4; y1 = rp[2] >> 4; x2 = rp[3] >> 4; y2 = rp[4] >> 4;
    }
    int* o = g_roi + r * 8;
    o[0] = b; o[1] = x1; o[2] = y1; o[3] = x2 - x1 + 1; o[4] = y2 - y1 + 1;
}

// ---------------- pool: block=(r, ph, c-half), thread=channel ----------------
__global__ __launch_bounds__(128)
void roipool3_kernel(float* __restrict__ out)
{
    const int r  = blockIdx.x;
    const int ph = blockIdx.y;
    const int c  = blockIdx.z * 128 + threadIdx.x;

    const int4 rb = *(const int4*)(g_roi + r * 8);   // b,x1,y1,w
    const int  h  = g_roi[r * 8 + 4];
    const int  b = rb.x, x1 = rb.y, y1 = rb.z, w = rb.w;

    const int sh = y1 + (ph * h) / RP_PH;
    const int eh = y1 + (((ph + 1) * h + (RP_PH - 1)) / RP_PH);

    const float* __restrict__ base = g_featT + ((size_t)b * RP_P) * RP_C + c;
    float* __restrict__ op = out + ((size_t)(r * RP_C + c) * RP_PH + ph) * RP_PW;

    const float NEGINF = -__int_as_float(0x7f800000);

    #pragma unroll
    for (int pw = 0; pw < RP_PW; ++pw) {
        const int sw = x1 + (pw * w) / RP_PW;
        const int ew = x1 + (((pw + 1) * w + (RP_PW - 1)) / RP_PW);
        const int bw = ew - sw;                       // 1..8, block-uniform

        // clamped column offsets (duplicates are in-bin: max idempotent)
        const int o1 = (1 < bw ? 1 : bw - 1) * RP_C;
        const int o2 = (2 < bw ? 2 : bw - 1) * RP_C;
        const int o3 = (3 < bw ? 3 : bw - 1) * RP_C;

        float m = NEGINF;
        for (int y = sh; y < eh; ++y) {
            const float* q = base + (y * RP_W + sw) * RP_C;
            const float v0 = __ldg(q);
            const float v1 = __ldg(q + o1);
            const float v2 = __ldg(q + o2);
            const float v3 = __ldg(q + o3);
            m = fmaxf(m, fmaxf(fmaxf(v0, v1), fmaxf(v2, v3)));
            for (int x = 4; x < bw; ++x)              // rare: bw in 5..8
                m = fmaxf(m, __ldg(q + x * RP_C));
        }
        op[pw] = m;
    }
}

extern "C" void kernel_launch(void* const* d_in, const int* in_sizes, int n_in,
                              void* d_out, int out_size)
{
    const float* feat   = (const float*)d_in[0];
    const int*   rois32 = (const int*)d_in[1];
    float*       out    = (float*)d_out;

    dim3 tgrid((RP_P + 31) / 32, RP_C / 32, RP_B);   // 79 x 8 x 4
    transpose_kernel<<<tgrid, 256>>>(feat);

    decode_rois_kernel<<<1, 256>>>(rois32);

    dim3 pgrid(RP_R, RP_PH, 2);                       // 256 x 7 x 2
    roipool3_kernel<<<pgrid, 128>>>(out);
}

// round 6
// speedup vs baseline: 1.3551x; 1.3551x over previous
#include <cuda_runtime.h>
#include <cstdint>

// ROI max pooling (shapes fixed):
//   features: (B=4, C=256, H=50, W=50) fp32;  rois: (R=256,5) int32/int64-sniffed
//   out: (R=256, C=256, PH=7, PW=7) fp32
//
// 1) transpose features -> g_featT[b][p][c] (p=y*W+x), float4 + XOR-swizzled
//    smem tiles (conflict-free both phases).
// 2) pool: block = 1 warp = (r, ph, c-half of 128). Each lane owns 4 channels
//    (float4). Per x-bin: 4 clamped LDG.128 per row (dupes hit L1), fmax tree.
//    Outputs staged in smem, written with lane-interleaved indices so stores
//    merge within the 28B-per-(c,ph) output chunks.

#define RP_B  4
#define RP_C  256
#define RP_H  50
#define RP_W  50
#define RP_P  (RP_H * RP_W)   // 2500
#define RP_R  256
#define RP_PH 7
#define RP_PW 7

__device__ float g_featT[RP_B * RP_P * RP_C];   // 10.24 MB scratch

__device__ __forceinline__ float4 f4max(float4 a, float4 b) {
    return make_float4(fmaxf(a.x, b.x), fmaxf(a.y, b.y),
                       fmaxf(a.z, b.z), fmaxf(a.w, b.w));
}

// ---------------- transpose: (B,C,P) -> (B,P,C) ----------------
// tile: 32 channels x 128 positions. smem stored as float4 columns with
// XOR swizzle: float4-col' = lane ^ (c & 31)  -> conflict-free STS.128 and
// conflict-free column LDS.32.
__global__ __launch_bounds__(256)
void transpose_kernel(const float* __restrict__ feat)
{
    __shared__ float tile[32 * 128];          // [c][p] with swizzled float4 cols
    const int b  = blockIdx.z;
    const int ct = blockIdx.y;                // 0..7
    const int pt = blockIdx.x;                // 0..19
    const int lane = threadIdx.x & 31;
    const int ty   = threadIdx.x >> 5;        // 0..7

    const int c0 = ct * 32;
    const int p0 = pt * 128;

    // read: 4 c-rows per warp-row; lane covers 4 p via float4
    #pragma unroll
    for (int i = 0; i < 4; ++i) {
        const int cr = ty + 8 * i;            // 0..31
        const int p  = p0 + 4 * lane;
        if (p + 3 < RP_P) {
            const float4 v = __ldg((const float4*)(feat +
                                 ((size_t)(b * RP_C + c0 + cr)) * RP_P + p));
            const int col = lane ^ cr;        // swizzled float4 column
            *(float4*)&tile[cr * 128 + 4 * col] = v;
        } else {
            // ragged tail of last p-tile: scalar, guarded
            #pragma unroll
            for (int j = 0; j < 4; ++j) {
                const int pp = p + j;
                if (pp < RP_P) {
                    const float v = __ldg(feat +
                        ((size_t)(b * RP_C + c0 + cr)) * RP_P + pp);
                    const int col = (lane ^ cr);
                    tile[cr * 128 + 4 * col + j] = v;
                }
            }
        }
    }
    __syncthreads();

    // write: lane = channel, 16 p-rows per thread
    #pragma unroll
    for (int i = 0; i < 16; ++i) {
        const int p = i * 8 + ty;             // 0..127
        if (p0 + p < RP_P) {
            const int col = (p >> 2) ^ lane;  // unswizzle
            const float v = tile[lane * 128 + 4 * col + (p & 3)];
            g_featT[((size_t)b * RP_P + p0 + p) * RP_C + c0 + lane] = v;
        }
    }
}

// ---------------- pool: 1 warp per (r, ph, c-half) ----------------
__global__ __launch_bounds__(32)
void roipool4_kernel(const int* __restrict__ rois32,
                     float* __restrict__ out)
{
    const int r    = blockIdx.x;
    const int ph   = blockIdx.y;
    const int zh   = blockIdx.z;              // channel half: 0/1
    const int lane = threadIdx.x;

    __shared__ float sbuf[RP_PW][132];        // [pw][c_local], 16B-aligned rows

    // dtype sniff (uniform, L1-broadcast): int64 => all odd words zero
    int odd = 0;
    #pragma unroll
    for (int i = 0; i < 16; ++i) odd |= __ldg(rois32 + 2 * i + 1);

    int b, x1, y1, w, h;
    if (odd == 0) {
        const int* rp = rois32 + r * 10;
        b  = __ldg(rp);
        x1 = __ldg(rp + 2) >> 4;  y1 = __ldg(rp + 4) >> 4;
        w  = (__ldg(rp + 6) >> 4) - x1 + 1;
        h  = (__ldg(rp + 8) >> 4) - y1 + 1;
    } else {
        const int* rp = rois32 + r * 5;
        b  = __ldg(rp);
        x1 = __ldg(rp + 1) >> 4;  y1 = __ldg(rp + 2) >> 4;
        w  = (__ldg(rp + 3) >> 4) - x1 + 1;
        h  = (__ldg(rp + 4) >> 4) - y1 + 1;
    }

    const int sh = y1 + (ph * h) / RP_PH;
    const int eh = y1 + (((ph + 1) * h + (RP_PH - 1)) / RP_PH);

    // float4 view of g_featT: index = p*64 + c/4 ; this lane: c = zh*128+4*lane
    const float4* __restrict__ base =
        (const float4*)g_featT + ((size_t)b * RP_P) * (RP_C / 4) + zh * 32 + lane;

    const float NEG = __int_as_float(0xff800000);  // -inf

    #pragma unroll
    for (int pw = 0; pw < RP_PW; ++pw) {
        const int sw = x1 + (pw * w) / RP_PW;
        const int ew = x1 + (((pw + 1) * w + (RP_PW - 1)) / RP_PW);
        const int bw = ew - sw;                            // 1..~8, uniform

        const int o1 = min(1, bw - 1) * (RP_C / 4);
        const int o2 = min(2, bw - 1) * (RP_C / 4);
        const int o3 = min(3, bw - 1) * (RP_C / 4);

        const float4* q = base + (sh * RP_W + sw) * (RP_C / 4);
        float4 acc = make_float4(NEG, NEG, NEG, NEG);

        for (int y = sh; y < eh; ++y) {
            float4 v0 = __ldg(q);
            float4 v1 = __ldg(q + o1);
            float4 v2 = __ldg(q + o2);
            float4 v3 = __ldg(q + o3);
            for (int x = 4; x < bw; ++x)                   // rare tail
                v1 = f4max(v1, __ldg(q + x * (RP_C / 4)));
            v0 = f4max(v0, v1);
            v2 = f4max(v2, v3);
            acc = f4max(acc, f4max(v0, v2));
            q += RP_W * (RP_C / 4);
        }
        *(float4*)&sbuf[pw][4 * lane] = acc;
    }
    __syncwarp();

    // staged write-out: interleaved so lane stores merge within 28B chunks
    const int ch0 = zh * 128;
    float* __restrict__ ob =
        out + ((size_t)(r * RP_C + ch0) * RP_PH + ph) * RP_PW;
    #pragma unroll
    for (int k = 0; k < 28; ++k) {
        const unsigned idx = k * 32 + lane;        // 0..895
        const unsigned cl = idx / 7;
        const unsigned pw = idx % 7;
        ob[cl * (RP_PH * RP_PW) + pw] = sbuf[pw][cl];
    }
}

extern "C" void kernel_launch(void* const* d_in, const int* in_sizes, int n_in,
                              void* d_out, int out_size)
{
    const float* feat   = (const float*)d_in[0];
    const int*   rois32 = (const int*)d_in[1];
    float*       out    = (float*)d_out;

    dim3 tgrid((RP_P + 127) / 128, RP_C / 32, RP_B);   // 20 x 8 x 4
    transpose_kernel<<<tgrid, 256>>>(feat);

    dim3 pgrid(RP_R, RP_PH, 2);                         // 256 x 7 x 2
    roipool4_kernel<<<pgrid, 32>>>(rois32, out);
}